// round 3
// baseline (speedup 1.0000x reference)
#include <cuda_runtime.h>

// Problem shape (fixed by the dataset):
// x: (B=8, C=64, T=2048, J=64) fp32; Ci=32.
// Inputs (metadata order): x, w_g, b_g, w_theta, b_theta, w_phi, b_phi, proj, w_out, b_out

#define TT 8   // t-values per CTA

// Precomputed fused weights:
//   Q[j,k]  = sum_c proj[j,c]    * w_theta[c,k]      (theta conv folded into projection)
//   R[j,k]  = sum_c proj[j,32+c] * w_phi[c,k]        (phi conv folded into projection)
//   ab[j]   = sum_c proj[j,c]*b_theta[c] + proj[j,32+c]*b_phi[c]
__device__ float g_Qd[64 * 64];
__device__ float g_Rd[64 * 64];
__device__ float g_abd[64];

__global__ void prep_kernel(const float* __restrict__ w_theta,
                            const float* __restrict__ b_theta,
                            const float* __restrict__ w_phi,
                            const float* __restrict__ b_phi,
                            const float* __restrict__ proj) {
    const int tid = threadIdx.x;
    for (int idx = tid; idx < 4096; idx += 256) {
        const int j = idx >> 6, k = idx & 63;
        float q = 0.f, r = 0.f;
#pragma unroll
        for (int c = 0; c < 32; c++) {
            q += proj[j * 64 + c]      * w_theta[c * 64 + k];
            r += proj[j * 64 + 32 + c] * w_phi[c * 64 + k];
        }
        g_Qd[idx] = q;
        g_Rd[idx] = r;
    }
    if (tid < 64) {
        float s = 0.f;
#pragma unroll
        for (int c = 0; c < 32; c++)
            s += proj[tid * 64 + c] * b_theta[c] + proj[tid * 64 + 32 + c] * b_phi[c];
        g_abd[tid] = s;
    }
}

// Shared-memory layout (floats)
#define OFF_RT  0        // Rt [64][68]   Rt[k][j] = R[j][k]
#define OFF_Q   4352     // Qs [64][65]   Qs[j][k]
#define OFF_WGT 8512     // Wgt[64][36]   Wgt[k][o] = w_g[o][k]
#define OFF_WOT 10816    // Wot[32][68]   Wot[o][c] = w_out[c][o]
#define OFF_XS  12992    // xs [64][64]   xs[c][j]
#define OFF_FT  17088    // ft [64][68]   ft[i][j]  = f[j][i]   (f scaled by 1/64)
#define OFF_GT  21440    // gt [64][36]   gt[i][o]  = g[o][i]
#define OFF_YT  23744    // yt [32][68]   yt[o][j]  = y[j][o]
#define OFF_A   25920    // a  [64]
#define OFF_BG  25984    // b_g[32]
#define OFF_BO  26016    // b_out[64]
#define SMEM_FLOATS 26080
#define SMEM_BYTES (SMEM_FLOATS * 4)

__global__ __launch_bounds__(256, 2)
void tnl_kernel(const float* __restrict__ x,
                const float* __restrict__ w_g,
                const float* __restrict__ b_g,
                const float* __restrict__ w_out,
                const float* __restrict__ b_out,
                float* __restrict__ out) {
    extern __shared__ float sm[];
    float* Rt  = sm + OFF_RT;
    float* Qs  = sm + OFF_Q;
    float* Wgt = sm + OFF_WGT;
    float* Wot = sm + OFF_WOT;
    float* xs  = sm + OFF_XS;
    float* ft  = sm + OFF_FT;
    float* gt  = sm + OFF_GT;
    float* yt  = sm + OFF_YT;
    float* avec = sm + OFF_A;
    float* bgs = sm + OFF_BG;
    float* bos = sm + OFF_BO;

    const int tid = threadIdx.x;

    // ---- load constants (once per CTA) ----
    for (int idx = tid; idx < 4096; idx += 256) {
        const int j = idx >> 6, k = idx & 63;
        Rt[k * 68 + j] = g_Rd[idx];
        Qs[j * 65 + k] = g_Qd[idx];
    }
    for (int idx = tid; idx < 2048; idx += 256) {
        const int o = idx >> 6, k = idx & 63;
        Wgt[k * 36 + o] = w_g[idx];          // w_g[o][k]
        const int c = idx >> 5, o2 = idx & 31;
        Wot[o2 * 68 + c] = w_out[idx];       // w_out[c][o2]
    }
    if (tid < 32) bgs[tid] = b_g[tid];
    if (tid < 64) bos[tid] = b_out[tid];
    __syncthreads();

    const int bIdx = blockIdx.x >> 8;            // 256 t-chunks per batch
    const int t0 = (blockIdx.x & 255) * TT;

    for (int tt = 0; tt < TT; tt++) {
        const int t = t0 + tt;

        // ---- load x tile: xs[c][j] = x[b,c,t,j] ----
        {
            const int f4 = tid & 15;
#pragma unroll
            for (int it = 0; it < 4; it++) {
                const int c = (tid >> 4) + it * 16;
                const float4 v = *(const float4*)(x + (((size_t)(bIdx * 64 + c) * 2048 + t) << 6) + f4 * 4);
                *(float4*)(xs + c * 64 + f4 * 4) = v;
            }
        }
        __syncthreads();

        // ---- phase 1: g = W_g @ x + b_g (threads 0..127), a[j] (threads 128..191) ----
        if (tid < 128) {
            const int i0 = (tid & 15) * 4;
            const int o0 = (tid >> 4) * 4;
            float acc[4][4] = {};
#pragma unroll 4
            for (int k = 0; k < 64; k++) {
                const float4 wv = *(const float4*)(Wgt + k * 36 + o0);
                const float4 xv = *(const float4*)(xs + k * 64 + i0);
                acc[0][0] += wv.x * xv.x; acc[0][1] += wv.x * xv.y; acc[0][2] += wv.x * xv.z; acc[0][3] += wv.x * xv.w;
                acc[1][0] += wv.y * xv.x; acc[1][1] += wv.y * xv.y; acc[1][2] += wv.y * xv.z; acc[1][3] += wv.y * xv.w;
                acc[2][0] += wv.z * xv.x; acc[2][1] += wv.z * xv.y; acc[2][2] += wv.z * xv.z; acc[2][3] += wv.z * xv.w;
                acc[3][0] += wv.w * xv.x; acc[3][1] += wv.w * xv.y; acc[3][2] += wv.w * xv.z; acc[3][3] += wv.w * xv.w;
            }
            const float b0 = bgs[o0], b1 = bgs[o0 + 1], b2 = bgs[o0 + 2], b3 = bgs[o0 + 3];
#pragma unroll
            for (int bc = 0; bc < 4; bc++) {
                float4 v;
                v.x = acc[0][bc] + b0; v.y = acc[1][bc] + b1;
                v.z = acc[2][bc] + b2; v.w = acc[3][bc] + b3;
                *(float4*)(gt + (i0 + bc) * 36 + o0) = v;   // gt[i][o]
            }
        } else if (tid < 192) {
            const int j = tid - 128;
            float s = g_abd[j];
#pragma unroll 8
            for (int k = 0; k < 64; k++)
                s += Qs[j * 65 + k] * xs[k * 64 + j];
            avec[j] = s;
        }
        __syncthreads();

        // ---- phase 2: f[j][i] = relu(a[j] + (R@x)[j][i]) / 64, stored transposed ----
        {
            const int i0 = (tid & 15) * 4;
            const int j0 = (tid >> 4) * 4;
            float acc[4][4] = {};
#pragma unroll 4
            for (int k = 0; k < 64; k++) {
                const float4 rv = *(const float4*)(Rt + k * 68 + j0);
                const float4 xv = *(const float4*)(xs + k * 64 + i0);
                acc[0][0] += rv.x * xv.x; acc[0][1] += rv.x * xv.y; acc[0][2] += rv.x * xv.z; acc[0][3] += rv.x * xv.w;
                acc[1][0] += rv.y * xv.x; acc[1][1] += rv.y * xv.y; acc[1][2] += rv.y * xv.z; acc[1][3] += rv.y * xv.w;
                acc[2][0] += rv.z * xv.x; acc[2][1] += rv.z * xv.y; acc[2][2] += rv.z * xv.z; acc[2][3] += rv.z * xv.w;
                acc[3][0] += rv.w * xv.x; acc[3][1] += rv.w * xv.y; acc[3][2] += rv.w * xv.z; acc[3][3] += rv.w * xv.w;
            }
            const float a0 = avec[j0], a1 = avec[j0 + 1], a2 = avec[j0 + 2], a3 = avec[j0 + 3];
#pragma unroll
            for (int bc = 0; bc < 4; bc++) {
                float4 v;
                v.x = fmaxf(acc[0][bc] + a0, 0.f) * 0.015625f;
                v.y = fmaxf(acc[1][bc] + a1, 0.f) * 0.015625f;
                v.z = fmaxf(acc[2][bc] + a2, 0.f) * 0.015625f;
                v.w = fmaxf(acc[3][bc] + a3, 0.f) * 0.015625f;
                *(float4*)(ft + (i0 + bc) * 68 + j0) = v;   // ft[i][j]
            }
        }
        __syncthreads();

        // ---- phase 3: y[j][o] = sum_i f[j][i] * g[o][i], stored transposed ----
        {
            const int o0 = (tid & 15) * 2;
            const int j0 = (tid >> 4) * 4;
            float acc[4][2] = {};
#pragma unroll 4
            for (int k = 0; k < 64; k++) {
                const float4 fv = *(const float4*)(ft + k * 68 + j0);
                const float2 gv = *(const float2*)(gt + k * 36 + o0);
                acc[0][0] += fv.x * gv.x; acc[0][1] += fv.x * gv.y;
                acc[1][0] += fv.y * gv.x; acc[1][1] += fv.y * gv.y;
                acc[2][0] += fv.z * gv.x; acc[2][1] += fv.z * gv.y;
                acc[3][0] += fv.w * gv.x; acc[3][1] += fv.w * gv.y;
            }
#pragma unroll
            for (int bc = 0; bc < 2; bc++) {
                float4 v;
                v.x = acc[0][bc]; v.y = acc[1][bc]; v.z = acc[2][bc]; v.w = acc[3][bc];
                *(float4*)(yt + (o0 + bc) * 68 + j0) = v;   // yt[o][j]
            }
        }
        __syncthreads();

        // ---- phase 4: out[c][j] = sum_o W_out[c][o]*y[j][o] + b_out[c] + x[c][j] ----
        {
            const int j0 = (tid & 15) * 4;
            const int c0 = (tid >> 4) * 4;
            float acc[4][4] = {};
#pragma unroll 4
            for (int o = 0; o < 32; o++) {
                const float4 wv = *(const float4*)(Wot + o * 68 + c0);
                const float4 yv = *(const float4*)(yt + o * 68 + j0);
                acc[0][0] += wv.x * yv.x; acc[0][1] += wv.x * yv.y; acc[0][2] += wv.x * yv.z; acc[0][3] += wv.x * yv.w;
                acc[1][0] += wv.y * yv.x; acc[1][1] += wv.y * yv.y; acc[1][2] += wv.y * yv.z; acc[1][3] += wv.y * yv.w;
                acc[2][0] += wv.z * yv.x; acc[2][1] += wv.z * yv.y; acc[2][2] += wv.z * yv.z; acc[2][3] += wv.z * yv.w;
                acc[3][0] += wv.w * yv.x; acc[3][1] += wv.w * yv.y; acc[3][2] += wv.w * yv.z; acc[3][3] += wv.w * yv.w;
            }
#pragma unroll
            for (int a = 0; a < 4; a++) {
                const int c = c0 + a;
                const float bo = bos[c];
                const float4 xv = *(const float4*)(xs + c * 64 + j0);
                float4 v;
                v.x = acc[a][0] + bo + xv.x;
                v.y = acc[a][1] + bo + xv.y;
                v.z = acc[a][2] + bo + xv.z;
                v.w = acc[a][3] + bo + xv.w;
                *(float4*)(out + (((size_t)(bIdx * 64 + c) * 2048 + t) << 6) + j0) = v;
            }
        }
        __syncthreads();   // protect xs before next iteration's load
    }
}

extern "C" void kernel_launch(void* const* d_in, const int* in_sizes, int n_in,
                              void* d_out, int out_size) {
    const float* x       = (const float*)d_in[0];
    const float* w_g     = (const float*)d_in[1];
    const float* b_g     = (const float*)d_in[2];
    const float* w_theta = (const float*)d_in[3];
    const float* b_theta = (const float*)d_in[4];
    const float* w_phi   = (const float*)d_in[5];
    const float* b_phi   = (const float*)d_in[6];
    const float* proj    = (const float*)d_in[7];
    const float* w_out   = (const float*)d_in[8];
    const float* b_out   = (const float*)d_in[9];
    float* out = (float*)d_out;

    prep_kernel<<<1, 256>>>(w_theta, b_theta, w_phi, b_phi, proj);

    cudaFuncSetAttribute(tnl_kernel, cudaFuncAttributeMaxDynamicSharedMemorySize, SMEM_BYTES);
    // grid: 8 batches * (2048 / TT) t-chunks = 2048 CTAs
    tnl_kernel<<<8 * (2048 / TT), 256, SMEM_BYTES>>>(x, w_g, b_g, w_out, b_out, out);
}

// round 6
// speedup vs baseline: 1.0036x; 1.0036x over previous
#include <cuda_runtime.h>

// Problem shape (fixed by the dataset):
// x: (B=8, C=64, T=2048, J=64) fp32; Ci=32.
// Inputs (metadata order): x, w_g, b_g, w_theta, b_theta, w_phi, b_phi, proj, w_out, b_out

#define TT 8   // t-values per CTA

// Precomputed fused weights:
//   Q[j,k]  = sum_c proj[j,c]    * w_theta[c,k]      (theta conv folded into projection)
//   R[j,k]  = sum_c proj[j,32+c] * w_phi[c,k]        (phi conv folded into projection)
//   ab[j]   = sum_c proj[j,c]*b_theta[c] + proj[j,32+c]*b_phi[c]
__device__ float g_Qd[64 * 64];
__device__ float g_Rd[64 * 64];
__device__ float g_abd[64];

__global__ void prep_kernel(const float* __restrict__ w_theta,
                            const float* __restrict__ b_theta,
                            const float* __restrict__ w_phi,
                            const float* __restrict__ b_phi,
                            const float* __restrict__ proj) {
    const int tid = threadIdx.x;
    for (int idx = tid; idx < 4096; idx += 256) {
        const int j = idx >> 6, k = idx & 63;
        float q = 0.f, r = 0.f;
#pragma unroll
        for (int c = 0; c < 32; c++) {
            q += proj[j * 64 + c]      * w_theta[c * 64 + k];
            r += proj[j * 64 + 32 + c] * w_phi[c * 64 + k];
        }
        g_Qd[idx] = q;
        g_Rd[idx] = r;
    }
    if (tid < 64) {
        float s = 0.f;
#pragma unroll
        for (int c = 0; c < 32; c++)
            s += proj[tid * 64 + c] * b_theta[c] + proj[tid * 64 + 32 + c] * b_phi[c];
        g_abd[tid] = s;
    }
}

// Shared-memory layout (floats)
#define OFF_RT  0        // Rt [64][68]   Rt[k][j] = R[j][k]
#define OFF_Q   4352     // Qs [64][65]   Qs[j][k]
#define OFF_WGT 8512     // Wgt[64][36]   Wgt[k][o] = w_g[o][k]
#define OFF_WOT 10816    // Wot[32][68]   Wot[o][c] = w_out[c][o]
#define OFF_XS  12992    // xs [64][64]   xs[c][j]
#define OFF_FT  17088    // ft [64][68]   ft[i][j]  = f[j][i]   (f scaled by 1/64)
#define OFF_GT  21440    // gt [64][36]   gt[i][o]  = g[o][i]
#define OFF_YT  23744    // yt [32][68]   yt[o][j]  = y[j][o]
#define OFF_A   25920    // a  [64]
#define OFF_BG  25984    // b_g[32]
#define OFF_BO  26016    // b_out[64]
#define SMEM_FLOATS 26080
#define SMEM_BYTES (SMEM_FLOATS * 4)

__global__ __launch_bounds__(256, 2)
void tnl_kernel(const float* __restrict__ x,
                const float* __restrict__ w_g,
                const float* __restrict__ b_g,
                const float* __restrict__ w_out,
                const float* __restrict__ b_out,
                float* __restrict__ out) {
    extern __shared__ float sm[];
    float* Rt  = sm + OFF_RT;
    float* Qs  = sm + OFF_Q;
    float* Wgt = sm + OFF_WGT;
    float* Wot = sm + OFF_WOT;
    float* xs  = sm + OFF_XS;
    float* ft  = sm + OFF_FT;
    float* gt  = sm + OFF_GT;
    float* yt  = sm + OFF_YT;
    float* avec = sm + OFF_A;
    float* bgs = sm + OFF_BG;
    float* bos = sm + OFF_BO;

    const int tid = threadIdx.x;

    // ---- load constants (once per CTA) ----
    for (int idx = tid; idx < 4096; idx += 256) {
        const int j = idx >> 6, k = idx & 63;
        Rt[k * 68 + j] = g_Rd[idx];
        Qs[j * 65 + k] = g_Qd[idx];
    }
    for (int idx = tid; idx < 2048; idx += 256) {
        const int o = idx >> 6, k = idx & 63;
        Wgt[k * 36 + o] = w_g[idx];          // w_g[o][k]
        const int c = idx >> 5, o2 = idx & 31;
        Wot[o2 * 68 + c] = w_out[idx];       // w_out[c][o2]
    }
    if (tid < 32) bgs[tid] = b_g[tid];
    if (tid < 64) bos[tid] = b_out[tid];
    __syncthreads();

    const int bIdx = blockIdx.x >> 8;            // 256 t-chunks per batch
    const int t0 = (blockIdx.x & 255) * TT;

    for (int tt = 0; tt < TT; tt++) {
        const int t = t0 + tt;

        // ---- load x tile: xs[c][j] = x[b,c,t,j] ----
        {
            const int f4 = tid & 15;
#pragma unroll
            for (int it = 0; it < 4; it++) {
                const int c = (tid >> 4) + it * 16;
                const float4 v = *(const float4*)(x + (((size_t)(bIdx * 64 + c) * 2048 + t) << 6) + f4 * 4);
                *(float4*)(xs + c * 64 + f4 * 4) = v;
            }
        }
        __syncthreads();

        // ---- phase 1: g = W_g @ x + b_g (threads 0..127), a[j] (threads 128..191) ----
        if (tid < 128) {
            const int i0 = (tid & 15) * 4;
            const int o0 = (tid >> 4) * 4;
            float acc[4][4] = {};
#pragma unroll 4
            for (int k = 0; k < 64; k++) {
                const float4 wv = *(const float4*)(Wgt + k * 36 + o0);
                const float4 xv = *(const float4*)(xs + k * 64 + i0);
                acc[0][0] += wv.x * xv.x; acc[0][1] += wv.x * xv.y; acc[0][2] += wv.x * xv.z; acc[0][3] += wv.x * xv.w;
                acc[1][0] += wv.y * xv.x; acc[1][1] += wv.y * xv.y; acc[1][2] += wv.y * xv.z; acc[1][3] += wv.y * xv.w;
                acc[2][0] += wv.z * xv.x; acc[2][1] += wv.z * xv.y; acc[2][2] += wv.z * xv.z; acc[2][3] += wv.z * xv.w;
                acc[3][0] += wv.w * xv.x; acc[3][1] += wv.w * xv.y; acc[3][2] += wv.w * xv.z; acc[3][3] += wv.w * xv.w;
            }
            const float b0 = bgs[o0], b1 = bgs[o0 + 1], b2 = bgs[o0 + 2], b3 = bgs[o0 + 3];
#pragma unroll
            for (int bc = 0; bc < 4; bc++) {
                float4 v;
                v.x = acc[0][bc] + b0; v.y = acc[1][bc] + b1;
                v.z = acc[2][bc] + b2; v.w = acc[3][bc] + b3;
                *(float4*)(gt + (i0 + bc) * 36 + o0) = v;   // gt[i][o]
            }
        } else if (tid < 192) {
            const int j = tid - 128;
            float s = g_abd[j];
#pragma unroll 8
            for (int k = 0; k < 64; k++)
                s += Qs[j * 65 + k] * xs[k * 64 + j];
            avec[j] = s;
        }
        __syncthreads();

        // ---- phase 2: f[j][i] = relu(a[j] + (R@x)[j][i]) / 64, stored transposed ----
        {
            const int i0 = (tid & 15) * 4;
            const int j0 = (tid >> 4) * 4;
            float acc[4][4] = {};
#pragma unroll 4
            for (int k = 0; k < 64; k++) {
                const float4 rv = *(const float4*)(Rt + k * 68 + j0);
                const float4 xv = *(const float4*)(xs + k * 64 + i0);
                acc[0][0] += rv.x * xv.x; acc[0][1] += rv.x * xv.y; acc[0][2] += rv.x * xv.z; acc[0][3] += rv.x * xv.w;
                acc[1][0] += rv.y * xv.x; acc[1][1] += rv.y * xv.y; acc[1][2] += rv.y * xv.z; acc[1][3] += rv.y * xv.w;
                acc[2][0] += rv.z * xv.x; acc[2][1] += rv.z * xv.y; acc[2][2] += rv.z * xv.z; acc[2][3] += rv.z * xv.w;
                acc[3][0] += rv.w * xv.x; acc[3][1] += rv.w * xv.y; acc[3][2] += rv.w * xv.z; acc[3][3] += rv.w * xv.w;
            }
            const float a0 = avec[j0], a1 = avec[j0 + 1], a2 = avec[j0 + 2], a3 = avec[j0 + 3];
#pragma unroll
            for (int bc = 0; bc < 4; bc++) {
                float4 v;
                v.x = fmaxf(acc[0][bc] + a0, 0.f) * 0.015625f;
                v.y = fmaxf(acc[1][bc] + a1, 0.f) * 0.015625f;
                v.z = fmaxf(acc[2][bc] + a2, 0.f) * 0.015625f;
                v.w = fmaxf(acc[3][bc] + a3, 0.f) * 0.015625f;
                *(float4*)(ft + (i0 + bc) * 68 + j0) = v;   // ft[i][j]
            }
        }
        __syncthreads();

        // ---- phase 3: y[j][o] = sum_i f[j][i] * g[o][i], stored transposed ----
        {
            const int o0 = (tid & 15) * 2;
            const int j0 = (tid >> 4) * 4;
            float acc[4][2] = {};
#pragma unroll 4
            for (int k = 0; k < 64; k++) {
                const float4 fv = *(const float4*)(ft + k * 68 + j0);
                const float2 gv = *(const float2*)(gt + k * 36 + o0);
                acc[0][0] += fv.x * gv.x; acc[0][1] += fv.x * gv.y;
                acc[1][0] += fv.y * gv.x; acc[1][1] += fv.y * gv.y;
                acc[2][0] += fv.z * gv.x; acc[2][1] += fv.z * gv.y;
                acc[3][0] += fv.w * gv.x; acc[3][1] += fv.w * gv.y;
            }
#pragma unroll
            for (int bc = 0; bc < 2; bc++) {
                float4 v;
                v.x = acc[0][bc]; v.y = acc[1][bc]; v.z = acc[2][bc]; v.w = acc[3][bc];
                *(float4*)(yt + (o0 + bc) * 68 + j0) = v;   // yt[o][j]
            }
        }
        __syncthreads();

        // ---- phase 4: out[c][j] = sum_o W_out[c][o]*y[j][o] + b_out[c] + x[c][j] ----
        {
            const int j0 = (tid & 15) * 4;
            const int c0 = (tid >> 4) * 4;
            float acc[4][4] = {};
#pragma unroll 4
            for (int o = 0; o < 32; o++) {
                const float4 wv = *(const float4*)(Wot + o * 68 + c0);
                const float4 yv = *(const float4*)(yt + o * 68 + j0);
                acc[0][0] += wv.x * yv.x; acc[0][1] += wv.x * yv.y; acc[0][2] += wv.x * yv.z; acc[0][3] += wv.x * yv.w;
                acc[1][0] += wv.y * yv.x; acc[1][1] += wv.y * yv.y; acc[1][2] += wv.y * yv.z; acc[1][3] += wv.y * yv.w;
                acc[2][0] += wv.z * yv.x; acc[2][1] += wv.z * yv.y; acc[2][2] += wv.z * yv.z; acc[2][3] += wv.z * yv.w;
                acc[3][0] += wv.w * yv.x; acc[3][1] += wv.w * yv.y; acc[3][2] += wv.w * yv.z; acc[3][3] += wv.w * yv.w;
            }
#pragma unroll
            for (int a = 0; a < 4; a++) {
                const int c = c0 + a;
                const float bo = bos[c];
                const float4 xv = *(const float4*)(xs + c * 64 + j0);
                float4 v;
                v.x = acc[a][0] + bo + xv.x;
                v.y = acc[a][1] + bo + xv.y;
                v.z = acc[a][2] + bo + xv.z;
                v.w = acc[a][3] + bo + xv.w;
                *(float4*)(out + (((size_t)(bIdx * 64 + c) * 2048 + t) << 6) + j0) = v;
            }
        }
        __syncthreads();   // protect xs before next iteration's load
    }
}

extern "C" void kernel_launch(void* const* d_in, const int* in_sizes, int n_in,
                              void* d_out, int out_size) {
    const float* x       = (const float*)d_in[0];
    const float* w_g     = (const float*)d_in[1];
    const float* b_g     = (const float*)d_in[2];
    const float* w_theta = (const float*)d_in[3];
    const float* b_theta = (const float*)d_in[4];
    const float* w_phi   = (const float*)d_in[5];
    const float* b_phi   = (const float*)d_in[6];
    const float* proj    = (const float*)d_in[7];
    const float* w_out   = (const float*)d_in[8];
    const float* b_out   = (const float*)d_in[9];
    float* out = (float*)d_out;

    prep_kernel<<<1, 256>>>(w_theta, b_theta, w_phi, b_phi, proj);

    cudaFuncSetAttribute(tnl_kernel, cudaFuncAttributeMaxDynamicSharedMemorySize, SMEM_BYTES);
    // grid: 8 batches * (2048 / TT) t-chunks = 2048 CTAs
    tnl_kernel<<<8 * (2048 / TT), 256, SMEM_BYTES>>>(x, w_g, b_g, w_out, b_out, out);
}

// round 9
// speedup vs baseline: 2.0447x; 2.0372x over previous
#include <cuda_runtime.h>
#include <cstdint>

// ============================================================================
// TemNonLocalBlock via mma.sync tf32 (HMMA, plain sm_103-compatible PTX).
// x: (B=8, C=64, T=2048, J=64) fp32, Ci=32.
// Fused algebra per t-tile (X = x[b,:,t,:] as xs[c][j]):
//   D1[96x64] = W1 @ X          (W1 rows 0-63 = R = P2@Wphi, rows 64-95 = Wg)
//   a[j]      = ab[j] + sum_k Q[j][k] * xs[k][j]     (exact fp32, Q = P1@Wtheta)
//   f[j][i]   = relu(a[j] + D1[j][i]) / 64 ;  g'[o][i] = D1[64+o][i] + bg[o]
//   y[j][o]   = sum_i f[j][i] * g'[o][i]
//   out[c][j] = sum_o Wout[c][o] * y[j][o] + bo[c] + xs[c][j]   (residual exact)
// All GEMMs via mma.sync.aligned.m16n8k8.row.col.f32.tf32.tf32.f32.
// R9 fix: gt stride 36 -> 68 (was overflowing: i index runs 0..63).
// ============================================================================

__device__ float g_W1[96 * 64];   // tf32-rounded bits stored as float
__device__ float g_Wo[64 * 32];   // tf32-rounded
__device__ float g_Qd[64 * 64];   // exact fp32
__device__ float g_abd[64];

__device__ __forceinline__ uint32_t tf32r(float f) {
    uint32_t u;
    asm("cvt.rna.tf32.f32 %0, %1;" : "=r"(u) : "f"(f));
    return u;
}

__global__ void prep_kernel(const float* __restrict__ w_g,
                            const float* __restrict__ w_theta,
                            const float* __restrict__ b_theta,
                            const float* __restrict__ w_phi,
                            const float* __restrict__ b_phi,
                            const float* __restrict__ proj,
                            const float* __restrict__ w_out) {
    const int tid = threadIdx.x;
    for (int idx = tid; idx < 96 * 64; idx += 256) {
        const int r = idx >> 6, k = idx & 63;
        float v;
        if (r < 64) {
            v = 0.f;
#pragma unroll
            for (int c = 0; c < 32; c++)
                v += proj[r * 64 + 32 + c] * w_phi[c * 64 + k];
        } else {
            v = w_g[(r - 64) * 64 + k];
        }
        g_W1[idx] = __uint_as_float(tf32r(v));
    }
    for (int idx = tid; idx < 4096; idx += 256) {
        const int j = idx >> 6, k = idx & 63;
        float q = 0.f;
#pragma unroll
        for (int c = 0; c < 32; c++)
            q += proj[j * 64 + c] * w_theta[c * 64 + k];
        g_Qd[idx] = q;
    }
    for (int idx = tid; idx < 64 * 32; idx += 256)
        g_Wo[idx] = __uint_as_float(tf32r(w_out[idx]));
    if (tid < 64) {
        float s = 0.f;
#pragma unroll
        for (int c = 0; c < 32; c++)
            s += proj[tid * 64 + c] * b_theta[c] + proj[tid * 64 + 32 + c] * b_phi[c];
        g_abd[tid] = s;
    }
}

// mma.sync m16n8k8 tf32: D += A*B.  A 4 regs, B 2 regs, D 4 f32.
#define MMA_TF32(d, a, b0, b1)                                                  \
    asm volatile("mma.sync.aligned.m16n8k8.row.col.f32.tf32.tf32.f32 "          \
                 "{%0,%1,%2,%3}, {%4,%5,%6,%7}, {%8,%9}, {%0,%1,%2,%3};"        \
                 : "+f"((d)[0]), "+f"((d)[1]), "+f"((d)[2]), "+f"((d)[3])       \
                 : "r"((a)[0]), "r"((a)[1]), "r"((a)[2]), "r"((a)[3]),          \
                   "r"(b0), "r"(b1))

// ---- SMEM layout (floats). Strides chosen for conflict-free fragment LDS:
//   stride % 32 == 4  (bank = 4*g + tig distinct)  for W1/Q/fs/gt (68)
//   stride % 32 == 8  (bank = 8*tig + g distinct)  for xs (72)
//   stride % 32 == 4  for Wos/ys (36)
#define OFF_W1   0        // [96][68]
#define OFF_Q    6528     // [64][68]
#define OFF_WO   10880    // [64][36]
#define OFF_XS   13184    // [64][72]  xs[c][j]  (exact fp32; raw bits as tf32 B)
#define OFF_FS   17792    // [64][68]  f[j][i]   tf32-rounded
#define OFF_GT   22144    // [32][68]  g'[o][i]  tf32-rounded   (FIXED stride)
#define OFF_YS   24320    // [64][36]  y[j][o]   tf32-rounded
#define OFF_AV   26624    // [64]
#define OFF_BG   26688    // [32]
#define OFF_BO   26720    // [64]
#define OFF_AB   26784    // [64]
#define SMEM_FLOATS 26848
#define SMEM_BYTES (SMEM_FLOATS * 4)

#define TT 8   // t per CTA

__global__ __launch_bounds__(256, 2)
void tnl_mma_kernel(const float* __restrict__ x,
                    const float* __restrict__ b_g,
                    const float* __restrict__ b_out,
                    float* __restrict__ out) {
    extern __shared__ float sm[];
    float* W1s = sm + OFF_W1;
    float* Qs  = sm + OFF_Q;
    float* Wos = sm + OFF_WO;
    float* xs  = sm + OFF_XS;
    float* fs  = sm + OFF_FS;
    float* gt  = sm + OFF_GT;
    float* ys  = sm + OFF_YS;
    float* avec = sm + OFF_AV;
    float* bgs = sm + OFF_BG;
    float* bos = sm + OFF_BO;
    float* abv = sm + OFF_AB;

    const int tid = threadIdx.x;
    const int w = tid >> 5, lid = tid & 31;
    const int g = lid >> 2, tg = lid & 3;

    // ---- CTA-wide constant staging ----
    for (int i = tid; i < 96 * 64; i += 256) W1s[(i >> 6) * 68 + (i & 63)] = g_W1[i];
    for (int i = tid; i < 64 * 64; i += 256) Qs[(i >> 6) * 68 + (i & 63)] = g_Qd[i];
    for (int i = tid; i < 64 * 32; i += 256) Wos[(i >> 5) * 36 + (i & 31)] = g_Wo[i];
    if (tid < 32) bgs[tid] = b_g[tid];
    if (tid < 64) { bos[tid] = b_out[tid]; abv[tid] = g_abd[tid]; }
    __syncthreads();

    const int bIdx = blockIdx.x >> 8;
    const int t0 = (blockIdx.x & 255) * TT;

    for (int tt = 0; tt < TT; tt++) {
        const int t = t0 + tt;

        // ---- stage xs[c][j] = x[b,c,t,j] (exact fp32) ----
#pragma unroll
        for (int it = 0; it < 4; it++) {
            const int idx = it * 256 + tid;
            const int f4 = idx & 15, c = idx >> 4;
            const float4 v = *(const float4*)(x + (((size_t)(bIdx * 64 + c) * 2048 + t) << 6) + f4 * 4);
            *(float4*)(xs + c * 72 + f4 * 4) = v;
        }
        __syncthreads();

        // ================= phase 1 =================
        float acc1[8][4];
        if (w < 6) {
            // warp w owns m-tile w of D1 (rows 16w..16w+15), all 64 cols
            uint32_t Af[8][4];
            {
                const float* Ar = W1s + (w * 16 + g) * 68 + tg;
#pragma unroll
                for (int k0 = 0; k0 < 8; k0++) {
                    Af[k0][0] = __float_as_uint(Ar[k0 * 8]);
                    Af[k0][1] = __float_as_uint(Ar[8 * 68 + k0 * 8]);
                    Af[k0][2] = __float_as_uint(Ar[k0 * 8 + 4]);
                    Af[k0][3] = __float_as_uint(Ar[8 * 68 + k0 * 8 + 4]);
                }
            }
#pragma unroll
            for (int nt = 0; nt < 8; nt++) {
                acc1[nt][0] = acc1[nt][1] = acc1[nt][2] = acc1[nt][3] = 0.f;
                const float* Bc = xs + tg * 72 + nt * 8 + g;
#pragma unroll
                for (int k0 = 0; k0 < 8; k0++) {
                    const uint32_t b0 = __float_as_uint(Bc[k0 * 576]);
                    const uint32_t b1 = __float_as_uint(Bc[k0 * 576 + 288]);
                    MMA_TF32(acc1[nt], Af[k0], b0, b1);
                }
            }
        } else {
            // warps 6,7: exact fp32 diagonal a[j]
            const int j = tid - 192;
            float s = abv[j];
#pragma unroll 8
            for (int k = 0; k < 64; k++)
                s += Qs[j * 68 + k] * xs[k * 72 + j];
            avec[j] = s;
        }
        __syncthreads();

        // phase-1 epilogue: f (warps 0-3) / g' (warps 4,5)
        if (w < 4) {
            const int j0 = w * 16 + g;
            const float a0 = avec[j0], a1 = avec[j0 + 8];
#pragma unroll
            for (int nt = 0; nt < 8; nt++) {
                const int i = nt * 8 + 2 * tg;
                uint2 v0, v1;
                v0.x = tf32r(fmaxf(acc1[nt][0] + a0, 0.f) * 0.015625f);
                v0.y = tf32r(fmaxf(acc1[nt][1] + a0, 0.f) * 0.015625f);
                v1.x = tf32r(fmaxf(acc1[nt][2] + a1, 0.f) * 0.015625f);
                v1.y = tf32r(fmaxf(acc1[nt][3] + a1, 0.f) * 0.015625f);
                *(uint2*)(fs + j0 * 68 + i) = v0;
                *(uint2*)(fs + (j0 + 8) * 68 + i) = v1;
            }
        } else if (w < 6) {
            const int o0 = (w - 4) * 16 + g;
            const float b0v = bgs[o0], b1v = bgs[o0 + 8];
#pragma unroll
            for (int nt = 0; nt < 8; nt++) {
                const int i = nt * 8 + 2 * tg;
                uint2 v0, v1;
                v0.x = tf32r(acc1[nt][0] + b0v);
                v0.y = tf32r(acc1[nt][1] + b0v);
                v1.x = tf32r(acc1[nt][2] + b1v);
                v1.y = tf32r(acc1[nt][3] + b1v);
                *(uint2*)(gt + o0 * 68 + i) = v0;
                *(uint2*)(gt + (o0 + 8) * 68 + i) = v1;
            }
        }
        __syncthreads();

        // ================= phase 3: y = f @ g'^T  (M=64,N=32,K=64) =========
        {
            const int mt = w & 3, nh = w >> 2;
            uint32_t Af[8][4];
            {
                const float* Ar = fs + (mt * 16 + g) * 68 + tg;
#pragma unroll
                for (int k0 = 0; k0 < 8; k0++) {
                    Af[k0][0] = __float_as_uint(Ar[k0 * 8]);
                    Af[k0][1] = __float_as_uint(Ar[8 * 68 + k0 * 8]);
                    Af[k0][2] = __float_as_uint(Ar[k0 * 8 + 4]);
                    Af[k0][3] = __float_as_uint(Ar[8 * 68 + k0 * 8 + 4]);
                }
            }
            float acc3[2][4];
#pragma unroll
            for (int n2 = 0; n2 < 2; n2++) {
                const int nt = nh * 2 + n2;
                acc3[n2][0] = acc3[n2][1] = acc3[n2][2] = acc3[n2][3] = 0.f;
                const float* Bc = gt + (nt * 8 + g) * 68 + tg;
#pragma unroll
                for (int k0 = 0; k0 < 8; k0++) {
                    const uint32_t b0 = __float_as_uint(Bc[k0 * 8]);
                    const uint32_t b1 = __float_as_uint(Bc[k0 * 8 + 4]);
                    MMA_TF32(acc3[n2], Af[k0], b0, b1);
                }
            }
            __syncthreads();
            const int j0 = mt * 16 + g;
#pragma unroll
            for (int n2 = 0; n2 < 2; n2++) {
                const int o = (nh * 2 + n2) * 8 + 2 * tg;
                uint2 v0, v1;
                v0.x = tf32r(acc3[n2][0]); v0.y = tf32r(acc3[n2][1]);
                v1.x = tf32r(acc3[n2][2]); v1.y = tf32r(acc3[n2][3]);
                *(uint2*)(ys + j0 * 36 + o) = v0;
                *(uint2*)(ys + (j0 + 8) * 36 + o) = v1;
            }
        }
        __syncthreads();

        // ======== phase 4: out = Wout @ y^T + bo + x  (M=64,N=64,K=32) =====
        {
            const int mt = w & 3, nh = w >> 2;
            uint32_t Af[4][4];
            {
                const float* Ar = Wos + (mt * 16 + g) * 36 + tg;
#pragma unroll
                for (int k0 = 0; k0 < 4; k0++) {
                    Af[k0][0] = __float_as_uint(Ar[k0 * 8]);
                    Af[k0][1] = __float_as_uint(Ar[8 * 36 + k0 * 8]);
                    Af[k0][2] = __float_as_uint(Ar[k0 * 8 + 4]);
                    Af[k0][3] = __float_as_uint(Ar[8 * 36 + k0 * 8 + 4]);
                }
            }
            const int c0 = mt * 16 + g;
            const float bo0 = bos[c0], bo1 = bos[c0 + 8];
#pragma unroll
            for (int n2 = 0; n2 < 4; n2++) {
                const int nt = nh * 4 + n2;
                float acc4[4] = {0.f, 0.f, 0.f, 0.f};
                const float* Bc = ys + (nt * 8 + g) * 36 + tg;
#pragma unroll
                for (int k0 = 0; k0 < 4; k0++) {
                    const uint32_t b0 = __float_as_uint(Bc[k0 * 8]);
                    const uint32_t b1 = __float_as_uint(Bc[k0 * 8 + 4]);
                    MMA_TF32(acc4, Af[k0], b0, b1);
                }
                const int j = nt * 8 + 2 * tg;
                const float2 x0 = *(const float2*)(xs + c0 * 72 + j);
                const float2 x1 = *(const float2*)(xs + (c0 + 8) * 72 + j);
                float2 o0, o1;
                o0.x = acc4[0] + bo0 + x0.x;  o0.y = acc4[1] + bo0 + x0.y;
                o1.x = acc4[2] + bo1 + x1.x;  o1.y = acc4[3] + bo1 + x1.y;
                float* obase = out + (((size_t)(bIdx * 64) * 2048 + t) << 6);
                *(float2*)(obase + (size_t)c0 * 2048 * 64 + j) = o0;
                *(float2*)(obase + (size_t)(c0 + 8) * 2048 * 64 + j) = o1;
            }
        }
        __syncthreads();   // protect xs before next t's staging
    }
}

extern "C" void kernel_launch(void* const* d_in, const int* in_sizes, int n_in,
                              void* d_out, int out_size) {
    const float* x       = (const float*)d_in[0];
    const float* w_g     = (const float*)d_in[1];
    const float* b_g     = (const float*)d_in[2];
    const float* w_theta = (const float*)d_in[3];
    const float* b_theta = (const float*)d_in[4];
    const float* w_phi   = (const float*)d_in[5];
    const float* b_phi   = (const float*)d_in[6];
    const float* proj    = (const float*)d_in[7];
    const float* w_out   = (const float*)d_in[8];
    const float* b_out   = (const float*)d_in[9];
    float* out = (float*)d_out;

    prep_kernel<<<1, 256>>>(w_g, w_theta, b_theta, w_phi, b_phi, proj, w_out);

    cudaFuncSetAttribute(tnl_mma_kernel, cudaFuncAttributeMaxDynamicSharedMemorySize, SMEM_BYTES);
    tnl_mma_kernel<<<8 * (2048 / TT), 256, SMEM_BYTES>>>(x, b_g, b_out, out);
}